// round 1
// baseline (speedup 1.0000x reference)
#include <cuda_runtime.h>
#include <cuda_bf16.h>
#include <cstdint>
#include <cstddef>

// Problem shape (fixed by the dataset)
constexpr int B_  = 32;     // batch (two stacked views of 16)
constexpr int T_  = 1000;   // time
constexpr int C_  = 512;    // encoder dim
constexpr int V_  = 2000;   // vocab (0 = blank)
constexpr int U_  = 100;    // max target length
constexpr int S_  = 201;    // 2U+1 extended states
constexpr int SP  = 224;    // padded S (7 warps)
constexpr int M_  = B_ * T_;   // 32000 GEMM rows
constexpr float NEGF = -1.0e30f;

// -------- scratch (device globals: no allocations allowed) --------
__device__ float  g_logits[(size_t)M_ * V_];       // 256 MB
__device__ float  g_lse[M_];                       // per-row logsumexp
__device__ float  g_lpext[(size_t)B_ * T_ * SP];   // gathered extended log-probs
__device__ double g_ctc_acc;
__device__ double g_cr_acc;

// -------- f32x2 packed-FMA helpers (PTX-only; doubles fp32 rate) --------
__device__ __forceinline__ unsigned long long pack2(float lo, float hi) {
    unsigned long long r;
    asm("mov.b64 %0, {%1, %2};" : "=l"(r) : "f"(lo), "f"(hi));
    return r;
}
__device__ __forceinline__ void unpack2(unsigned long long v, float& lo, float& hi) {
    asm("mov.b64 {%0, %1}, %2;" : "=f"(lo), "=f"(hi) : "l"(v));
}
__device__ __forceinline__ void ffma2(unsigned long long& c,
                                      unsigned long long a,
                                      unsigned long long b) {
    asm("fma.rn.f32x2 %0, %1, %2, %0;" : "+l"(c) : "l"(a), "l"(b));
}

// ===================== 1) GEMM: logits = enc @ W^T + b =====================
// M=32000, N=2000 (tiles padded to 2048), K=512. Both operands K-contiguous.
// 128x64 tile, BK=16, 256 threads, 8(M)x4(N) micro-tile as 4x4 f32x2 pairs.
__global__ __launch_bounds__(256) void gemm_kernel(const float* __restrict__ A,
                                                   const float* __restrict__ W,
                                                   const float* __restrict__ bias) {
    __shared__ float As[2][16][128 + 4];
    __shared__ float Bs[2][16][64 + 4];

    const int tid = threadIdx.x;
    const int bm  = blockIdx.y;
    const int bn  = blockIdx.x;
    const int m0  = bm * 128;
    const int n0  = bn * 64;
    const int tm  = tid >> 4;   // 0..15 -> 8 M rows each
    const int tn  = tid & 15;   // 0..15 -> 4 N cols each

    unsigned long long acc[4][4];
#pragma unroll
    for (int i = 0; i < 4; i++)
#pragma unroll
        for (int j = 0; j < 4; j++) acc[i][j] = 0ull;

    float4 ra[2], rb;

    auto loadA = [&](int kt) {
#pragma unroll
        for (int l = 0; l < 2; l++) {
            int fid = tid + l * 256;
            int row = fid >> 2, kq = fid & 3;
            ra[l] = *reinterpret_cast<const float4*>(
                &A[(size_t)(m0 + row) * C_ + kt * 16 + kq * 4]);
        }
    };
    auto loadB = [&](int kt) {
        int row = tid >> 2, kq = tid & 3;
        int n = n0 + row;
        if (n < V_)
            rb = *reinterpret_cast<const float4*>(&W[(size_t)n * C_ + kt * 16 + kq * 4]);
        else
            rb = make_float4(0.f, 0.f, 0.f, 0.f);
    };
    auto storeA = [&](int buf) {
#pragma unroll
        for (int l = 0; l < 2; l++) {
            int fid = tid + l * 256;
            int row = fid >> 2, kq = fid & 3;
            As[buf][kq * 4 + 0][row] = ra[l].x;
            As[buf][kq * 4 + 1][row] = ra[l].y;
            As[buf][kq * 4 + 2][row] = ra[l].z;
            As[buf][kq * 4 + 3][row] = ra[l].w;
        }
    };
    auto storeB = [&](int buf) {
        int row = tid >> 2, kq = tid & 3;
        Bs[buf][kq * 4 + 0][row] = rb.x;
        Bs[buf][kq * 4 + 1][row] = rb.y;
        Bs[buf][kq * 4 + 2][row] = rb.z;
        Bs[buf][kq * 4 + 3][row] = rb.w;
    };

    loadA(0); loadB(0);
    storeA(0); storeB(0);
    __syncthreads();

    int cur = 0;
    const int NKT = C_ / 16;  // 32
    for (int kt = 0; kt < NKT; kt++) {
        if (kt + 1 < NKT) { loadA(kt + 1); loadB(kt + 1); }
#pragma unroll
        for (int k = 0; k < 16; k++) {
            unsigned long long aa[4];
#pragma unroll
            for (int i = 0; i < 4; i++)
                aa[i] = *reinterpret_cast<const unsigned long long*>(
                    &As[cur][k][tm * 8 + i * 2]);
            float4 bq = *reinterpret_cast<const float4*>(&Bs[cur][k][tn * 4]);
            unsigned long long bb[4];
            bb[0] = pack2(bq.x, bq.x);
            bb[1] = pack2(bq.y, bq.y);
            bb[2] = pack2(bq.z, bq.z);
            bb[3] = pack2(bq.w, bq.w);
#pragma unroll
            for (int i = 0; i < 4; i++)
#pragma unroll
                for (int j = 0; j < 4; j++) ffma2(acc[i][j], aa[i], bb[j]);
        }
        if (kt + 1 < NKT) { storeA(cur ^ 1); storeB(cur ^ 1); }
        __syncthreads();
        cur ^= 1;
    }

    // epilogue: + bias, store
#pragma unroll
    for (int i = 0; i < 4; i++) {
        int m = m0 + tm * 8 + i * 2;
#pragma unroll
        for (int j = 0; j < 4; j++) {
            int n = n0 + tn * 4 + j;
            if (n < V_) {
                float lo, hi;
                unpack2(acc[i][j], lo, hi);
                float bv = __ldg(&bias[n]);
                g_logits[(size_t)m * V_ + n]       = lo + bv;
                g_logits[(size_t)(m + 1) * V_ + n] = hi + bv;
            }
        }
    }
}

// ===================== 2) per-row logsumexp =====================
__global__ __launch_bounds__(256) void lse_kernel() {
    const int row = blockIdx.x;
    const float* p = &g_logits[(size_t)row * V_];
    float m = NEGF, sse = 0.f;
    for (int v = threadIdx.x; v < V_; v += 256) {
        float x = p[v];
        if (x > m) { sse *= __expf(m - x); m = x; }
        sse += __expf(x - m);
    }
    __shared__ float sm[256], ss[256];
    sm[threadIdx.x] = m; ss[threadIdx.x] = sse;
    __syncthreads();
    for (int o = 128; o > 0; o >>= 1) {
        if (threadIdx.x < o) {
            float m1 = sm[threadIdx.x], s1 = ss[threadIdx.x];
            float m2 = sm[threadIdx.x + o], s2 = ss[threadIdx.x + o];
            float M = fmaxf(m1, m2);
            ss[threadIdx.x] = s1 * __expf(m1 - M) + s2 * __expf(m2 - M);
            sm[threadIdx.x] = M;
        }
        __syncthreads();
    }
    if (threadIdx.x == 0) g_lse[row] = sm[0] + __logf(ss[0]);
}

// ===================== 3) KL consistency term =====================
// For pair (b, b+16): row b gets exp(q)(q-p), row b+16 gets exp(p)(p-q).
__global__ __launch_bounds__(256) void kl_kernel(const int* __restrict__ lens) {
    const int t  = blockIdx.x;   // 0..T-1
    const int bp = blockIdx.y;   // 0..15
    const int lenA = lens[bp], lenB = lens[bp + 16];
    const bool doA = t < lenA, doB = t < lenB;
    if (!doA && !doB) return;

    const size_t rowP = (size_t)bp * T_ + t;
    const size_t rowQ = (size_t)(bp + 16) * T_ + t;
    const float* P = &g_logits[rowP * V_];
    const float* Q = &g_logits[rowQ * V_];
    const float Lp = g_lse[rowP], Lq = g_lse[rowQ];

    float accA = 0.f, accB = 0.f;
    for (int v = threadIdx.x; v < V_; v += 256) {
        float p = P[v] - Lp;
        float q = Q[v] - Lq;
        float d = q - p;
        accA += __expf(q) * d;    // output row bp
        accB -= __expf(p) * d;    // output row bp+16: exp(p)*(p-q)
    }
    float c = (doA ? accA : 0.f) + (doB ? accB : 0.f);

    // block reduce
    for (int o = 16; o > 0; o >>= 1) c += __shfl_down_sync(0xffffffffu, c, o);
    __shared__ float wsum[8];
    if ((threadIdx.x & 31) == 0) wsum[threadIdx.x >> 5] = c;
    __syncthreads();
    if (threadIdx.x == 0) {
        float tot = 0.f;
#pragma unroll
        for (int w = 0; w < 8; w++) tot += wsum[w];
        atomicAdd(&g_cr_acc, (double)tot);
    }
}

// ===================== 4) gather extended-label log-probs =====================
__global__ void gather_kernel(const int* __restrict__ targets) {
    int idx = blockIdx.x * blockDim.x + threadIdx.x;
    if (idx >= B_ * T_ * SP) return;
    int s  = idx % SP;
    int bt = idx / SP;
    int b  = bt / T_;
    float out;
    if (s < S_) {
        int e = (s & 1) ? targets[b * U_ + ((s - 1) >> 1)] : 0;
        out = g_logits[(size_t)bt * V_ + e] - g_lse[bt];
    } else {
        out = NEGF;
    }
    g_lpext[idx] = out;
}

// ===================== 5) CTC forward recursion =====================
__device__ __forceinline__ float logadd3(float a, float b, float c) {
    float m = fmaxf(a, fmaxf(b, c));
    return m + __logf(__expf(a - m) + __expf(b - m) + __expf(c - m));
}
__device__ __forceinline__ float logadd2(float a, float b) {
    float m = fmaxf(a, b);
    return m + __logf(__expf(a - m) + __expf(b - m));
}

__global__ __launch_bounds__(SP) void ctc_kernel(const int* __restrict__ targets,
                                                 const int* __restrict__ lens,
                                                 const int* __restrict__ tlens) {
    const int b = blockIdx.x;
    const int s = threadIdx.x;
    const int len = lens[b];

    __shared__ float alpha[2][SP];

    bool sk = false;
    if (s < S_ && (s & 1) && s >= 3)
        sk = targets[b * U_ + ((s - 1) >> 1)] != targets[b * U_ + ((s - 3) >> 1)];

    alpha[0][s] = (s < 2) ? g_lpext[(size_t)b * T_ * SP + s] : NEGF;
    __syncthreads();

    const size_t base = (size_t)b * T_ * SP + s;
    float pre[8];
#pragma unroll
    for (int j = 0; j < 8; j++) {
        int tp = 1 + j; if (tp >= T_) tp = T_ - 1;
        pre[j] = g_lpext[base + (size_t)tp * SP];
    }

    int cur = 0;
    for (int t0 = 1; t0 < len; t0 += 8) {
#pragma unroll
        for (int j = 0; j < 8; j++) {
            int t = t0 + j;
            float a = alpha[cur][s];
            float nv;
            if (t < len) {
                float a1 = (s >= 1) ? alpha[cur][s - 1] : NEGF;
                float a2 = sk ? alpha[cur][s - 2] : NEGF;
                nv = logadd3(a, a1, a2) + pre[j];
            } else {
                nv = a;
            }
            alpha[cur ^ 1][s] = nv;
            cur ^= 1;
            __syncthreads();
            int tp = t + 8; if (tp >= T_) tp = T_ - 1;  // prefetch 8 ahead
            pre[j] = g_lpext[base + (size_t)tp * SP];
        }
    }

    if (s == 0) {
        int e = 2 * tlens[b];
        float ab = alpha[cur][e];
        float al = alpha[cur][e > 0 ? e - 1 : 0];
        atomicAdd(&g_ctc_acc, (double)(-logadd2(ab, al)));
    }
}

// ===================== accumulator init / finalize =====================
__global__ void init_kernel() { g_ctc_acc = 0.0; g_cr_acc = 0.0; }

__global__ void finalize_kernel(float* out) {
    out[0] = (float)(0.5 * g_ctc_acc);
    out[1] = (float)(0.5 * g_cr_acc);
}

// ===================== launch =====================
extern "C" void kernel_launch(void* const* d_in, const int* in_sizes, int n_in,
                              void* d_out, int out_size) {
    const float* enc     = (const float*)d_in[0];  // (32,1000,512)
    const float* W       = (const float*)d_in[1];  // (2000,512)
    const float* bias    = (const float*)d_in[2];  // (2000,)
    const int*   lens    = (const int*)d_in[3];    // (32,)
    const int*   targets = (const int*)d_in[4];    // (32,100)
    const int*   tlens   = (const int*)d_in[5];    // (32,)
    float* out = (float*)d_out;

    init_kernel<<<1, 1>>>();

    dim3 gg((V_ + 63) / 64, M_ / 128);   // 32 x 250
    gemm_kernel<<<gg, 256>>>(enc, W, bias);

    lse_kernel<<<M_, 256>>>();

    gather_kernel<<<(B_ * T_ * SP + 255) / 256, 256>>>(targets);

    dim3 gk(T_, B_ / 2);                 // 1000 x 16
    kl_kernel<<<gk, 256>>>(lens);

    ctc_kernel<<<B_, SP>>>(targets, lens, tlens);

    finalize_kernel<<<1, 1>>>(out);
}

// round 3
// speedup vs baseline: 1.5091x; 1.5091x over previous
#include <cuda_runtime.h>
#include <cuda_bf16.h>
#include <cstdint>
#include <cstddef>

// Problem shape (fixed by the dataset)
constexpr int B_  = 32;
constexpr int T_  = 1000;
constexpr int C_  = 512;     // K
constexpr int V_  = 2000;    // N (logical)
constexpr int U_  = 100;
constexpr int S_  = 201;
constexpr int SP  = 224;
constexpr int M_  = B_ * T_; // 32000
constexpr int NPAD = 2048;
constexpr float NEGF = -1.0e30f;

// GEMM tiling (warp-level HMMA: mma.sync.m16n8k16 bf16)
constexpr int BM = 128;
constexpr int BN = 128;
constexpr int BK = 64;                  // bf16 elems per stage = 128B rows
constexpr int NSTG = C_ / BK;           // 8 k-stages
constexpr int NTILE = NPAD / BN;        // 16
constexpr int MTILE = M_ / BM;          // 250
constexpr int NPART = NTILE * 4;        // 64 lse partials (4 n-warps per tile)

// smem: stages at 1024 (3 x 64KB: Ah,Al,Bh,Bl of 16KB each), bias after
constexpr int SM_STAGE = 65536;
constexpr int SM_BIAS  = 1024 + 3 * SM_STAGE;        // 197632
constexpr int SM_TOTAL = SM_BIAS + 512;              // 198144

// -------- scratch (device globals: no allocations allowed) --------
__device__ float         g_logits[(size_t)M_ * V_];   // 256 MB
__device__ __nv_bfloat16 g_Ah[(size_t)M_ * C_];
__device__ __nv_bfloat16 g_Al[(size_t)M_ * C_];
__device__ __nv_bfloat16 g_Wh[(size_t)NPAD * C_];
__device__ __nv_bfloat16 g_Wl[(size_t)NPAD * C_];
__device__ float         g_pmax[NPART][M_];
__device__ float         g_psum[NPART][M_];
__device__ float         g_lse[M_];
__device__ float         g_lpext[(size_t)B_ * T_ * SP];
__device__ double        g_ctc_acc;
__device__ double        g_cr_acc;

// ===================== PTX helpers =====================
__device__ __forceinline__ uint32_t s2u(const void* p) {
    uint32_t a;
    asm("{ .reg .u64 t; cvta.to.shared.u64 t, %1; cvt.u32.u64 %0, t; }" : "=r"(a) : "l"(p));
    return a;
}
__device__ __forceinline__ void cpasync16(uint32_t dst, const void* src) {
    asm volatile("cp.async.cg.shared.global [%0], [%1], 16;" :: "r"(dst), "l"(src) : "memory");
}
__device__ __forceinline__ void ldsm4(uint32_t* r, uint32_t addr) {
    asm volatile("ldmatrix.sync.aligned.m8n8.x4.shared.b16 {%0,%1,%2,%3}, [%4];"
                 : "=r"(r[0]), "=r"(r[1]), "=r"(r[2]), "=r"(r[3]) : "r"(addr));
}
__device__ __forceinline__ void ldsm2(uint32_t* r, uint32_t addr) {
    asm volatile("ldmatrix.sync.aligned.m8n8.x2.shared.b16 {%0,%1}, [%2];"
                 : "=r"(r[0]), "=r"(r[1]) : "r"(addr));
}
__device__ __forceinline__ void mma16816(float* d, const uint32_t* a, const uint32_t* b) {
    asm volatile(
        "mma.sync.aligned.m16n8k16.row.col.f32.bf16.bf16.f32 "
        "{%0,%1,%2,%3}, {%4,%5,%6,%7}, {%8,%9}, {%0,%1,%2,%3};"
        : "+f"(d[0]), "+f"(d[1]), "+f"(d[2]), "+f"(d[3])
        : "r"(a[0]), "r"(a[1]), "r"(a[2]), "r"(a[3]), "r"(b[0]), "r"(b[1]));
}

// ===================== bf16-split conversion =====================
__device__ __forceinline__ void split4(float4 v, uint2& hi, uint2& lo) {
    __nv_bfloat16 h0 = __float2bfloat16(v.x), h1 = __float2bfloat16(v.y);
    __nv_bfloat16 h2 = __float2bfloat16(v.z), h3 = __float2bfloat16(v.w);
    __nv_bfloat16 l0 = __float2bfloat16(v.x - __bfloat162float(h0));
    __nv_bfloat16 l1 = __float2bfloat16(v.y - __bfloat162float(h1));
    __nv_bfloat16 l2 = __float2bfloat16(v.z - __bfloat162float(h2));
    __nv_bfloat16 l3 = __float2bfloat16(v.w - __bfloat162float(h3));
    __nv_bfloat162 ph0(h0, h1), ph1(h2, h3), pl0(l0, l1), pl1(l2, l3);
    hi.x = *reinterpret_cast<uint32_t*>(&ph0); hi.y = *reinterpret_cast<uint32_t*>(&ph1);
    lo.x = *reinterpret_cast<uint32_t*>(&pl0); lo.y = *reinterpret_cast<uint32_t*>(&pl1);
}

__global__ __launch_bounds__(256) void convA_kernel(const float* __restrict__ enc) {
    size_t i = (size_t)blockIdx.x * 256 + threadIdx.x;
    float4 v = reinterpret_cast<const float4*>(enc)[i];
    uint2 hi, lo; split4(v, hi, lo);
    reinterpret_cast<uint2*>(g_Ah)[i] = hi;
    reinterpret_cast<uint2*>(g_Al)[i] = lo;
}

__global__ __launch_bounds__(256) void convW_kernel(const float* __restrict__ W) {
    size_t i = (size_t)blockIdx.x * 256 + threadIdx.x;
    int row = (int)(i >> 7);             // 4*i / 512
    float4 v = make_float4(0.f, 0.f, 0.f, 0.f);
    if (row < V_) v = reinterpret_cast<const float4*>(W)[i];
    uint2 hi, lo; split4(v, hi, lo);
    reinterpret_cast<uint2*>(g_Wh)[i] = hi;
    reinterpret_cast<uint2*>(g_Wl)[i] = lo;
}

// ===================== HMMA GEMM + fused LSE partials =====================
// 128B-row XOR swizzle at 16B granularity: off = row*128 + (colbyte ^ ((row&7)<<4))
__global__ __launch_bounds__(256, 1) void gemm_tc(const float* __restrict__ bias) {
    extern __shared__ __align__(1024) char smem[];
    const uint32_t sbase = s2u(smem);
    const int tid  = threadIdx.x;
    const int lane = tid & 31;
    const int wid  = tid >> 5;
    const int wm   = (wid >> 2) * 64;   // warp m offset (0 / 64)
    const int wn   = (wid & 3) * 32;    // warp n offset (0..96)
    const int n0   = blockIdx.x * BN;
    const int m0   = blockIdx.y * BM;

    // bias tile -> smem
    float* sbias = reinterpret_cast<float*>(smem + SM_BIAS);
    if (tid < BN) sbias[tid] = (n0 + tid < V_) ? __ldg(&bias[n0 + tid]) : 0.f;

    auto issue_loads = [&](int s) {
        const uint32_t buf = sbase + 1024 + (uint32_t)(s % 3) * SM_STAGE;
        const int kt = s * BK;
#pragma unroll
        for (int i = 0; i < 4; i++) {
            int flat = tid + i * 256;
            int row = flat >> 3, cc = flat & 7;
            uint32_t off = (uint32_t)(row * 128 + ((cc * 16) ^ ((row & 7) << 4)));
            size_t ao = (size_t)(m0 + row) * C_ + kt + cc * 8;
            size_t wo = (size_t)(n0 + row) * C_ + kt + cc * 8;
            cpasync16(buf + off,         &g_Ah[ao]);
            cpasync16(buf + 16384 + off, &g_Al[ao]);
            cpasync16(buf + 32768 + off, &g_Wh[wo]);
            cpasync16(buf + 49152 + off, &g_Wl[wo]);
        }
        asm volatile("cp.async.commit_group;" ::: "memory");
    };

    float acc[4][4][4];
#pragma unroll
    for (int i = 0; i < 4; i++)
#pragma unroll
        for (int j = 0; j < 4; j++)
#pragma unroll
            for (int e = 0; e < 4; e++) acc[i][j][e] = 0.f;

    // per-lane ldmatrix offsets (within a stage buffer)
    const uint32_t xr = (uint32_t)((lane & 7) << 4);
    uint32_t offA[4], offB[4];
#pragma unroll
    for (int mi = 0; mi < 4; mi++) offA[mi] = (uint32_t)((wm + mi * 16 + (lane & 15)) * 128);
#pragma unroll
    for (int nj = 0; nj < 4; nj++) offB[nj] = (uint32_t)((wn + nj * 8 + (lane & 7)) * 128);
    const uint32_t cAh = (uint32_t)(16 * (lane >> 4));        // A k-half select
    const uint32_t cBh = (uint32_t)(16 * ((lane >> 3) & 1));  // B k-half select

    issue_loads(0);
    issue_loads(1);

    for (int s = 0; s < NSTG; s++) {
        if (s + 2 < NSTG) {
            issue_loads(s + 2);
            asm volatile("cp.async.wait_group 2;" ::: "memory");
        } else {
            asm volatile("cp.async.wait_group 0;" ::: "memory");
        }
        __syncthreads();

        const uint32_t stg = sbase + 1024 + (uint32_t)(s % 3) * SM_STAGE;
#pragma unroll
        for (int ks = 0; ks < 4; ks++) {
            const uint32_t cA = ((uint32_t)(32 * ks) + cAh) ^ xr;
            const uint32_t cB = ((uint32_t)(32 * ks) + cBh) ^ xr;
            uint32_t ah[4][4], al[4][4], bh[4][2], bl[4][2];
#pragma unroll
            for (int mi = 0; mi < 4; mi++) {
                ldsm4(ah[mi], stg + offA[mi] + cA);
                ldsm4(al[mi], stg + 16384 + offA[mi] + cA);
            }
#pragma unroll
            for (int nj = 0; nj < 4; nj++) {
                ldsm2(bh[nj], stg + 32768 + offB[nj] + cB);
                ldsm2(bl[nj], stg + 49152 + offB[nj] + cB);
            }
#pragma unroll
            for (int mi = 0; mi < 4; mi++)
#pragma unroll
                for (int nj = 0; nj < 4; nj++) mma16816(acc[mi][nj], ah[mi], bh[nj]);
#pragma unroll
            for (int mi = 0; mi < 4; mi++)
#pragma unroll
                for (int nj = 0; nj < 4; nj++) mma16816(acc[mi][nj], ah[mi], bl[nj]);
#pragma unroll
            for (int mi = 0; mi < 4; mi++)
#pragma unroll
                for (int nj = 0; nj < 4; nj++) mma16816(acc[mi][nj], al[mi], bh[nj]);
        }
        __syncthreads();
    }

    // ---- epilogue: bias + direct store + fused row max/sumexp partials ----
    const int pn = blockIdx.x * 4 + (wid & 3);   // lse partial slot
    const int q  = lane >> 2;                     // quad row
    const int c2 = 2 * (lane & 3);                // quad col pair

#pragma unroll
    for (int mi = 0; mi < 4; mi++) {
        float mx0 = NEGF, sm0 = 0.f;   // row wm+mi*16+q
        float mx1 = NEGF, sm1 = 0.f;   // row +8
#pragma unroll
        for (int nj = 0; nj < 4; nj++) {
            int nloc = wn + nj * 8 + c2;
            int n = n0 + nloc;
            float b0 = sbias[nloc], b1 = sbias[nloc + 1];
            float v00 = acc[mi][nj][0] + b0, v01 = acc[mi][nj][1] + b1;
            float v10 = acc[mi][nj][2] + b0, v11 = acc[mi][nj][3] + b1;
            if (n < V_) {
                int mr = m0 + wm + mi * 16 + q;
                *reinterpret_cast<float2*>(&g_logits[(size_t)mr * V_ + n])       = make_float2(v00, v01);
                *reinterpret_cast<float2*>(&g_logits[(size_t)(mr + 8) * V_ + n]) = make_float2(v10, v11);
                // online max/sum
                float a = fmaxf(v00, v01);
                if (a > mx0) { sm0 *= __expf(mx0 - a); mx0 = a; }
                sm0 += __expf(v00 - mx0) + __expf(v01 - mx0);
                float b = fmaxf(v10, v11);
                if (b > mx1) { sm1 *= __expf(mx1 - b); mx1 = b; }
                sm1 += __expf(v10 - mx1) + __expf(v11 - mx1);
            }
        }
        // merge across the 4 lanes of the quad (lanes 4q..4q+3)
#pragma unroll
        for (int d = 1; d <= 2; d <<= 1) {
            float mo = __shfl_xor_sync(0xffffffffu, mx0, d);
            float so = __shfl_xor_sync(0xffffffffu, sm0, d);
            float M = fmaxf(mx0, mo);
            sm0 = sm0 * __expf(mx0 - M) + so * __expf(mo - M);
            mx0 = M;
            mo = __shfl_xor_sync(0xffffffffu, mx1, d);
            so = __shfl_xor_sync(0xffffffffu, sm1, d);
            M = fmaxf(mx1, mo);
            sm1 = sm1 * __expf(mx1 - M) + so * __expf(mo - M);
            mx1 = M;
        }
        if ((lane & 3) == 0) {
            int mr = m0 + wm + mi * 16 + q;
            g_pmax[pn][mr]     = mx0;  g_psum[pn][mr]     = sm0;
            g_pmax[pn][mr + 8] = mx1;  g_psum[pn][mr + 8] = sm1;
        }
    }
}

// ===================== LSE combine =====================
__global__ __launch_bounds__(256) void lse_combine_kernel() {
    int m = blockIdx.x * 256 + threadIdx.x;
    if (m >= M_) return;
    float mx = NEGF;
#pragma unroll
    for (int p = 0; p < NPART; p++) mx = fmaxf(mx, g_pmax[p][m]);
    float s = 0.f;
#pragma unroll
    for (int p = 0; p < NPART; p++) s += g_psum[p][m] * __expf(g_pmax[p][m] - mx);
    g_lse[m] = mx + __logf(s);
}

// ===================== KL consistency term =====================
__global__ __launch_bounds__(256) void kl_kernel(const int* __restrict__ lens) {
    const int t  = blockIdx.x;
    const int bp = blockIdx.y;
    const int lenA = lens[bp], lenB = lens[bp + 16];
    const bool doA = t < lenA, doB = t < lenB;
    if (!doA && !doB) return;

    const size_t rowP = (size_t)bp * T_ + t;
    const size_t rowQ = (size_t)(bp + 16) * T_ + t;
    const float* P = &g_logits[rowP * V_];
    const float* Q = &g_logits[rowQ * V_];
    const float Lp = g_lse[rowP], Lq = g_lse[rowQ];

    float accA = 0.f, accB = 0.f;
    for (int v = threadIdx.x; v < V_; v += 256) {
        float p = P[v] - Lp;
        float q = Q[v] - Lq;
        float d = q - p;
        accA += __expf(q) * d;
        accB -= __expf(p) * d;
    }
    float c = (doA ? accA : 0.f) + (doB ? accB : 0.f);
    for (int o = 16; o > 0; o >>= 1) c += __shfl_down_sync(0xffffffffu, c, o);
    __shared__ float wsum[8];
    if ((threadIdx.x & 31) == 0) wsum[threadIdx.x >> 5] = c;
    __syncthreads();
    if (threadIdx.x == 0) {
        float tot = 0.f;
#pragma unroll
        for (int w = 0; w < 8; w++) tot += wsum[w];
        atomicAdd(&g_cr_acc, (double)tot);
    }
}

// ===================== gather extended-label log-probs =====================
__global__ void gather_kernel(const int* __restrict__ targets) {
    int idx = blockIdx.x * blockDim.x + threadIdx.x;
    if (idx >= B_ * T_ * SP) return;
    int s  = idx % SP;
    int bt = idx / SP;
    int b  = bt / T_;
    float out;
    if (s < S_) {
        int e = (s & 1) ? targets[b * U_ + ((s - 1) >> 1)] : 0;
        out = g_logits[(size_t)bt * V_ + e] - g_lse[bt];
    } else {
        out = NEGF;
    }
    g_lpext[idx] = out;
}

// ===================== CTC forward recursion =====================
__device__ __forceinline__ float logadd3(float a, float b, float c) {
    float m = fmaxf(a, fmaxf(b, c));
    return m + __logf(__expf(a - m) + __expf(b - m) + __expf(c - m));
}
__device__ __forceinline__ float logadd2(float a, float b) {
    float m = fmaxf(a, b);
    return m + __logf(__expf(a - m) + __expf(b - m));
}

__global__ __launch_bounds__(SP) void ctc_kernel(const int* __restrict__ targets,
                                                 const int* __restrict__ lens,
                                                 const int* __restrict__ tlens) {
    const int b = blockIdx.x;
    const int s = threadIdx.x;
    const int len = lens[b];

    __shared__ float alpha[2][SP];

    bool sk = false;
    if (s < S_ && (s & 1) && s >= 3)
        sk = targets[b * U_ + ((s - 1) >> 1)] != targets[b * U_ + ((s - 3) >> 1)];

    alpha[0][s] = (s < 2) ? g_lpext[(size_t)b * T_ * SP + s] : NEGF;
    __syncthreads();

    const size_t base = (size_t)b * T_ * SP + s;
    float pre[8];
#pragma unroll
    for (int j = 0; j < 8; j++) {
        int tp = 1 + j; if (tp >= T_) tp = T_ - 1;
        pre[j] = g_lpext[base + (size_t)tp * SP];
    }

    int cur = 0;
    for (int t0 = 1; t0 < len; t0 += 8) {
#pragma unroll
        for (int j = 0; j < 8; j++) {
            int t = t0 + j;
            float a = alpha[cur][s];
            float nv;
            if (t < len) {
                float a1 = (s >= 1) ? alpha[cur][s - 1] : NEGF;
                float a2 = sk ? alpha[cur][s - 2] : NEGF;
                nv = logadd3(a, a1, a2) + pre[j];
            } else {
                nv = a;
            }
            alpha[cur ^ 1][s] = nv;
            cur ^= 1;
            __syncthreads();
            int tp = t + 8; if (tp >= T_) tp = T_ - 1;
            pre[j] = g_lpext[base + (size_t)tp * SP];
        }
    }

    if (s == 0) {
        int e = 2 * tlens[b];
        float ab = alpha[cur][e];
        float al = alpha[cur][e > 0 ? e - 1 : 0];
        atomicAdd(&g_ctc_acc, (double)(-logadd2(ab, al)));
    }
}

// ===================== init / finalize =====================
__global__ void init_kernel() { g_ctc_acc = 0.0; g_cr_acc = 0.0; }
__global__ void finalize_kernel(float* out) {
    out[0] = (float)(0.5 * g_ctc_acc);
    out[1] = (float)(0.5 * g_cr_acc);
}

// ===================== launch =====================
extern "C" void kernel_launch(void* const* d_in, const int* in_sizes, int n_in,
                              void* d_out, int out_size) {
    const float* enc     = (const float*)d_in[0];
    const float* W       = (const float*)d_in[1];
    const float* bias    = (const float*)d_in[2];
    const int*   lens    = (const int*)d_in[3];
    const int*   targets = (const int*)d_in[4];
    const int*   tlens   = (const int*)d_in[5];
    float* out = (float*)d_out;

    cudaFuncSetAttribute(gemm_tc, cudaFuncAttributeMaxDynamicSharedMemorySize, SM_TOTAL);

    init_kernel<<<1, 1>>>();

    convA_kernel<<<(int)((size_t)M_ * C_ / 4 / 256), 256>>>(enc);
    convW_kernel<<<(int)((size_t)NPAD * C_ / 4 / 256), 256>>>(W);

    dim3 gg(NTILE, MTILE);   // 16 x 250
    gemm_tc<<<gg, 256, SM_TOTAL>>>(bias);

    lse_combine_kernel<<<(M_ + 255) / 256, 256>>>();

    gather_kernel<<<(B_ * T_ * SP + 255) / 256, 256>>>(targets);

    dim3 gk(T_, B_ / 2);
    kl_kernel<<<gk, 256>>>(lens);

    ctc_kernel<<<B_, SP>>>(targets, lens, tlens);

    finalize_kernel<<<1, 1>>>(out);
}